// round 2
// baseline (speedup 1.0000x reference)
#include <cuda_runtime.h>

// Seq2Seq LSTM autoencoder, persistent-block design.
// B=4096 rows split across 152 blocks (1/SM on GB300). Each block: 512
// threads, 8 row-groups x 64 threads (thread = hidden unit, owns all 4
// gates). State: c in registers, h in smem (double-buffered, stored
// duplicated as float2 for packed f32x2 FMA). Weights in smem as
// [k][unit][gate i,f,g,o] float4 (conflict-free LDS.128), phase-swapped
// encoder -> decoder.

#define NB 4096
#define TT 500
#define DD 32
#define HH 64
#define NGRID 152
#define NTHREADS 512
#define RMAX 27

#define SM_W4    0            // float4 [96*64]          = 98304 B
#define SM_WOUT  98304        // float  [64*32]          =  8192 B
#define SM_HS    106496       // float2 [2][27][64]      = 27648 B
#define SM_XS    134144       // float2 [2][27][32]      = 13824 B
#define SM_TOTAL 147968

typedef unsigned long long ull;

__device__ __forceinline__ ull pack2(float lo, float hi) {
    ull r; asm("mov.b64 %0, {%1, %2};" : "=l"(r) : "f"(lo), "f"(hi)); return r;
}
__device__ __forceinline__ void unpack2(float& lo, float& hi, ull v) {
    asm("mov.b64 {%0, %1}, %2;" : "=f"(lo), "=f"(hi) : "l"(v));
}
// Packed fp32x2 FMA (sm_100+; PTX-only, ptxas never auto-fuses)
#define FFMA2(acc, a, b) asm("fma.rn.f32x2 %0, %1, %2, %0;" : "+l"(acc) : "l"(a), "l"(b))

__device__ __forceinline__ float sigm(float v) {
    return __fdividef(1.f, 1.f + __expf(-v));
}
__device__ __forceinline__ float tanh_(float v) {
    return __fdividef(2.f, 1.f + __expf(-2.f * v)) - 1.f;
}

// One LSTM step for NR rows (rows rbase + i*8), unit u of each row.
// Reads xs (duplicated float2, [r][32]) and hs (duplicated float2, [r][64]),
// writes new h (duplicated) to hsn, updates c[i] in registers.
template<int NR>
__device__ __forceinline__ void lstm_rows(
    const float4* W4, const float2* xsb, const float2* hsb, float2* hsn,
    ull bif, ull bgo, float* c, int rbase, int u)
{
    ull aif[NR], ago[NR];
#pragma unroll
    for (int i = 0; i < NR; ++i) { aif[i] = bif; ago[i] = bgo; }
#pragma unroll 4
    for (int k = 0; k < DD; ++k) {
        ulonglong2 w = *reinterpret_cast<const ulonglong2*>(W4 + k * 64 + u);
#pragma unroll
        for (int i = 0; i < NR; ++i) {
            ull v = *reinterpret_cast<const ull*>(xsb + (rbase + i * 8) * DD + k);
            FFMA2(aif[i], w.x, v);
            FFMA2(ago[i], w.y, v);
        }
    }
#pragma unroll 4
    for (int k = 0; k < HH; ++k) {
        ulonglong2 w = *reinterpret_cast<const ulonglong2*>(W4 + (DD + k) * 64 + u);
#pragma unroll
        for (int i = 0; i < NR; ++i) {
            ull v = *reinterpret_cast<const ull*>(hsb + (rbase + i * 8) * HH + k);
            FFMA2(aif[i], w.x, v);
            FFMA2(ago[i], w.y, v);
        }
    }
#pragma unroll
    for (int i = 0; i < NR; ++i) {
        float ai, af, ag, ao;
        unpack2(ai, af, aif[i]);
        unpack2(ag, ao, ago[i]);
        float ig = sigm(ai), fg = sigm(af);
        float gg = tanh_(ag), og = sigm(ao);
        float cn = fg * c[i] + ig * gg;
        c[i] = cn;
        float h = og * tanh_(cn);
        hsn[(rbase + i * 8) * HH + u] = make_float2(h, h);
    }
}

__device__ __forceinline__ void load_gate_weights(
    float4* W4, const float* Wih, const float* Whh, int tid)
{
    for (int idx = tid; idx < 96 * 64; idx += NTHREADS) {
        int k = idx >> 6, uu = idx & 63;
        float4 w;
        if (k < DD) {
            w.x = Wih[(uu      ) * DD + k];
            w.y = Wih[(uu +  64) * DD + k];
            w.z = Wih[(uu + 128) * DD + k];
            w.w = Wih[(uu + 192) * DD + k];
        } else {
            int kk = k - DD;
            w.x = Whh[(uu      ) * HH + kk];
            w.y = Whh[(uu +  64) * HH + kk];
            w.z = Whh[(uu + 128) * HH + kk];
            w.w = Whh[(uu + 192) * HH + kk];
        }
        W4[idx] = w;
    }
}

__global__ void __launch_bounds__(NTHREADS, 1)
seq2seq_kernel(const float* __restrict__ x,
               const float* __restrict__ Wih_e, const float* __restrict__ Whh_e,
               const float* __restrict__ b_e,
               const float* __restrict__ Wih_d, const float* __restrict__ Whh_d,
               const float* __restrict__ b_d,
               const float* __restrict__ Wout, const float* __restrict__ bout,
               float* __restrict__ outp)
{
    extern __shared__ char sm[];
    float4* W4  = reinterpret_cast<float4*>(sm + SM_W4);
    float*  WoT = reinterpret_cast<float*>(sm + SM_WOUT);
    float2* hs  = reinterpret_cast<float2*>(sm + SM_HS);
    float2* xs  = reinterpret_cast<float2*>(sm + SM_XS);

    const int tid = threadIdx.x;
    const int u   = tid & 63;   // hidden unit
    const int grp = tid >> 6;   // row group 0..7
    const int bid = blockIdx.x;
    const int rstart = (bid * NB) / NGRID;
    const int cnt = ((bid + 1) * NB) / NGRID - rstart;  // 26 or 27 real rows

    // ---- encoder weights + init state ----
    load_gate_weights(W4, Wih_e, Whh_e, tid);
    for (int i = tid; i < RMAX * HH; i += NTHREADS) hs[i] = make_float2(0.f, 0.f);
    for (int i = tid; i < RMAX * DD; i += NTHREADS) {
        int r = i >> 5, d = i & 31;
        float v = 0.f;
        if (r < cnt) v = x[(size_t)(rstart + r) * (TT * DD) + d];  // t = 0
        xs[i] = make_float2(v, v);
    }
    ull bif = pack2(b_e[u], b_e[64 + u]);
    ull bgo = pack2(b_e[128 + u], b_e[192 + u]);
    float c_reg[4] = {0.f, 0.f, 0.f, 0.f};
    __syncthreads();

    int cur = 0;
    // ===== encoder: 500 steps, 1 sync/step =====
    for (int t = 0; t < TT; ++t) {
        const int nxt = cur ^ 1;
        // prefetch x for t+1 into registers (latency hidden under compute)
        float xv0 = 0.f, xv1 = 0.f;
        const bool pre = (t + 1 < TT);
        if (pre) {
            int r = tid >> 5, d = tid & 31;
            if (r < cnt) xv0 = x[(size_t)(rstart + r) * (TT * DD) + (size_t)(t + 1) * DD + d];
            if (tid + NTHREADS < RMAX * DD) {
                int i2 = tid + NTHREADS;
                int r2 = i2 >> 5, d2 = i2 & 31;
                if (r2 < cnt) xv1 = x[(size_t)(rstart + r2) * (TT * DD) + (size_t)(t + 1) * DD + d2];
            }
        }
        lstm_rows<3>(W4, xs + cur * (RMAX * DD), hs + cur * (RMAX * HH),
                     hs + nxt * (RMAX * HH), bif, bgo, c_reg, grp, u);
        if (grp < RMAX - 24)   // rows 24..26 (warp-uniform branch)
            lstm_rows<1>(W4, xs + cur * (RMAX * DD), hs + cur * (RMAX * HH),
                         hs + nxt * (RMAX * HH), bif, bgo, c_reg + 3, 24 + grp, u);
        if (pre) {
            xs[nxt * (RMAX * DD) + tid] = make_float2(xv0, xv0);
            if (tid + NTHREADS < RMAX * DD)
                xs[nxt * (RMAX * DD) + tid + NTHREADS] = make_float2(xv1, xv1);
        }
        __syncthreads();
        cur = nxt;
    }

    // ===== swap to decoder weights =====
    load_gate_weights(W4, Wih_d, Whh_d, tid);
    for (int idx = tid; idx < HH * DD; idx += NTHREADS) {
        int k = idx >> 5, d = idx & 31;
        WoT[idx] = Wout[d * HH + k];     // WoT[k][d] = Wout[d][k]
    }
    for (int i = tid; i < RMAX * DD; i += NTHREADS)
        xs[cur * (RMAX * DD) + i] = make_float2(0.f, 0.f);  // dec_in0 = 0
    bif = pack2(b_d[u], b_d[64 + u]);
    bgo = pack2(b_d[128 + u], b_d[192 + u]);
    const float bo = bout[u & 31];
    __syncthreads();

    // ===== decoder: 500 autoregressive steps, 2 syncs/step =====
    for (int t = 0; t < TT; ++t) {
        const int nxt = cur ^ 1;
        lstm_rows<3>(W4, xs + cur * (RMAX * DD), hs + cur * (RMAX * HH),
                     hs + nxt * (RMAX * HH), bif, bgo, c_reg, grp, u);
        if (grp < RMAX - 24)
            lstm_rows<1>(W4, xs + cur * (RMAX * DD), hs + cur * (RMAX * HH),
                         hs + nxt * (RMAX * HH), bif, bgo, c_reg + 3, 24 + grp, u);
        __syncthreads();

        // out = h @ Wout^T + bout; feeds next step's input.
        // Thread handles dim (u&31); half=u>>5 selects its 2 row-iters so all
        // SMSPs stay busy.
        {
            const int dd = u & 31;
            const int half = u >> 5;
#pragma unroll
            for (int j = 0; j < 2; ++j) {
                int r = grp + (half * 2 + j) * 8;
                if (r >= RMAX) break;   // warp-uniform
                float acc = bo;
                const float2* hrow = hs + nxt * (RMAX * HH) + r * HH;
#pragma unroll 8
                for (int k = 0; k < HH; ++k)
                    acc = fmaf(hrow[k].x, WoT[k * DD + dd], acc);
                if (r < cnt)
                    outp[(size_t)(rstart + r) * (TT * DD) + (size_t)t * DD + dd] = acc;
                xs[nxt * (RMAX * DD) + r * DD + dd] = make_float2(acc, acc);
            }
        }
        __syncthreads();
        cur = nxt;
    }
}

extern "C" void kernel_launch(void* const* d_in, const int* in_sizes, int n_in,
                              void* d_out, int out_size)
{
    (void)in_sizes; (void)n_in; (void)out_size;
    cudaFuncSetAttribute(seq2seq_kernel,
                         cudaFuncAttributeMaxDynamicSharedMemorySize, SM_TOTAL);
    seq2seq_kernel<<<NGRID, NTHREADS, SM_TOTAL>>>(
        (const float*)d_in[0],
        (const float*)d_in[1], (const float*)d_in[2], (const float*)d_in[3],
        (const float*)d_in[4], (const float*)d_in[5], (const float*)d_in[6],
        (const float*)d_in[7], (const float*)d_in[8],
        (float*)d_out);
}

// round 9
// speedup vs baseline: 1.3695x; 1.3695x over previous
#include <cuda_runtime.h>

// Seq2Seq LSTM autoencoder, persistent-block design. GB300: 152 SMs.
// 256 threads = 4 row-groups x 64 units (thread = hidden unit, all 4 gates).
// Rows/thread: 7 (groups 0-2) or 6 (group 3), stride 4. c in registers,
// h/x in smem DUPLICATED float2 so one LDS.128 broadcast yields two packed
// f32x2 operands. Weights [k][u][i,f,g,o] float4 in smem (conflict-free
// LDS.128), phase-swapped encoder -> decoder.

#define NB 4096
#define TT 500
#define DD 32
#define HH 64
#define NGRID 152
#define NTHREADS 256
#define RMAX 27

#define SM_W4    0            // float4 [96*64]            = 98304 B
#define SM_WOUT  98304        // float2 [32*32] (k-pairs)  =  8192 B
#define SM_HS    106496       // float2 [2][27][64]        = 27648 B
#define SM_XS    134144       // float2 [2][27][32]        = 13824 B
#define SM_TOTAL 147968

typedef unsigned long long ull;

__device__ __forceinline__ ull pack2(float lo, float hi) {
    ull r; asm("mov.b64 %0, {%1, %2};" : "=l"(r) : "f"(lo), "f"(hi)); return r;
}
__device__ __forceinline__ void unpack2(float& lo, float& hi, ull v) {
    asm("mov.b64 {%0, %1}, %2;" : "=f"(lo), "=f"(hi) : "l"(v));
}
// Packed fp32x2 FMA (sm_100+; PTX-only, ptxas never auto-fuses)
#define FFMA2(acc, a, b) asm("fma.rn.f32x2 %0, %1, %2, %0;" : "+l"(acc) : "l"(a), "l"(b))

__device__ __forceinline__ float sigm(float v) {
    return __fdividef(1.f, 1.f + __expf(-v));
}
__device__ __forceinline__ float tanh_(float v) {
    return __fdividef(2.f, 1.f + __expf(-2.f * v)) - 1.f;
}

// One LSTM step for NR rows (rbase + i*4), unit u. Reads duplicated pairs
// two-k-at-a-time via 16B broadcast loads.
template<int NR>
__device__ __forceinline__ void lstm_rows(
    const float4* W4, const float4* xs4, const float4* hs4, float2* hsn,
    ull bif, ull bgo, float* c, int rbase, int u)
{
    ull aif[NR], ago[NR];
#pragma unroll
    for (int i = 0; i < NR; ++i) { aif[i] = bif; ago[i] = bgo; }
#pragma unroll 4
    for (int kp = 0; kp < DD / 2; ++kp) {
        ulonglong2 w0 = *reinterpret_cast<const ulonglong2*>(W4 + (2 * kp    ) * 64 + u);
        ulonglong2 w1 = *reinterpret_cast<const ulonglong2*>(W4 + (2 * kp + 1) * 64 + u);
#pragma unroll
        for (int i = 0; i < NR; ++i) {
            ulonglong2 v = *reinterpret_cast<const ulonglong2*>(xs4 + (rbase + i * 4) * 16 + kp);
            FFMA2(aif[i], w0.x, v.x);
            FFMA2(ago[i], w0.y, v.x);
            FFMA2(aif[i], w1.x, v.y);
            FFMA2(ago[i], w1.y, v.y);
        }
    }
#pragma unroll 4
    for (int kp = 0; kp < HH / 2; ++kp) {
        ulonglong2 w0 = *reinterpret_cast<const ulonglong2*>(W4 + (DD + 2 * kp    ) * 64 + u);
        ulonglong2 w1 = *reinterpret_cast<const ulonglong2*>(W4 + (DD + 2 * kp + 1) * 64 + u);
#pragma unroll
        for (int i = 0; i < NR; ++i) {
            ulonglong2 v = *reinterpret_cast<const ulonglong2*>(hs4 + (rbase + i * 4) * 32 + kp);
            FFMA2(aif[i], w0.x, v.x);
            FFMA2(ago[i], w0.y, v.x);
            FFMA2(aif[i], w1.x, v.y);
            FFMA2(ago[i], w1.y, v.y);
        }
    }
#pragma unroll
    for (int i = 0; i < NR; ++i) {
        float ai, af, ag, ao;
        unpack2(ai, af, aif[i]);
        unpack2(ag, ao, ago[i]);
        float ig = sigm(ai), fg = sigm(af);
        float gg = tanh_(ag), og = sigm(ao);
        float cn = fg * c[i] + ig * gg;
        c[i] = cn;
        float h = og * tanh_(cn);
        hsn[(rbase + i * 4) * HH + u] = make_float2(h, h);
    }
}

// Decoder out-projection partial: k-pair outer, rows inner, f32x2 FMA.
template<int NRJ>
__device__ __forceinline__ void oproj_loop(
    ull* acc2, const float4* hs4n, const ull* WoT2u, const int* rj, int dd)
{
#pragma unroll 8
    for (int kp = 0; kp < HH / 2; ++kp) {
        ull wp = WoT2u[kp * DD + dd];
#pragma unroll
        for (int j = 0; j < NRJ; ++j) {
            float4 q = hs4n[rj[j] * 32 + kp];  // (hk,hk,hk1,hk1) broadcast
            ull hv = pack2(q.x, q.z);
            FFMA2(acc2[j], hv, wp);
        }
    }
}

__device__ __forceinline__ void load_gate_weights(
    float4* W4, const float* Wih, const float* Whh, int tid)
{
    for (int idx = tid; idx < 96 * 64; idx += NTHREADS) {
        int k = idx >> 6, uu = idx & 63;
        float4 w;
        if (k < DD) {
            w.x = Wih[(uu      ) * DD + k];
            w.y = Wih[(uu +  64) * DD + k];
            w.z = Wih[(uu + 128) * DD + k];
            w.w = Wih[(uu + 192) * DD + k];
        } else {
            int kk = k - DD;
            w.x = Whh[(uu      ) * HH + kk];
            w.y = Whh[(uu +  64) * HH + kk];
            w.z = Whh[(uu + 128) * HH + kk];
            w.w = Whh[(uu + 192) * HH + kk];
        }
        W4[idx] = w;
    }
}

__global__ void __launch_bounds__(NTHREADS, 1)
seq2seq_kernel(const float* __restrict__ x,
               const float* __restrict__ Wih_e, const float* __restrict__ Whh_e,
               const float* __restrict__ b_e,
               const float* __restrict__ Wih_d, const float* __restrict__ Whh_d,
               const float* __restrict__ b_d,
               const float* __restrict__ Wout, const float* __restrict__ bout,
               float* __restrict__ outp)
{
    extern __shared__ char sm[];
    float4*  W4    = reinterpret_cast<float4*>(sm + SM_W4);
    float2*  WoT2  = reinterpret_cast<float2*>(sm + SM_WOUT);
    const ull* WoT2u = reinterpret_cast<const ull*>(sm + SM_WOUT);
    float2*  hs2   = reinterpret_cast<float2*>(sm + SM_HS);
    float4*  hs4   = reinterpret_cast<float4*>(sm + SM_HS);
    float2*  xs2   = reinterpret_cast<float2*>(sm + SM_XS);
    float4*  xs4   = reinterpret_cast<float4*>(sm + SM_XS);

    const int tid = threadIdx.x;
    const int u   = tid & 63;   // hidden unit
    const int grp = tid >> 6;   // row group 0..3
    const int bid = blockIdx.x;
    const int rstart = (bid * NB) / NGRID;
    const int cnt = ((bid + 1) * NB) / NGRID - rstart;  // 26 or 27 real rows
    const bool seven = (grp < 3); // groups 0..2 own 7 rows (warp-uniform)

    // ---- encoder weights + init state ----
    load_gate_weights(W4, Wih_e, Whh_e, tid);
    for (int i = tid; i < 2 * RMAX * HH; i += NTHREADS) hs2[i] = make_float2(0.f, 0.f);
    for (int i = tid; i < RMAX * DD; i += NTHREADS) {
        int r = i >> 5, d = i & 31;
        float v = 0.f;
        if (r < cnt) v = x[(size_t)(rstart + r) * (TT * DD) + d];  // t = 0
        xs2[i] = make_float2(v, v);
    }
    ull bif = pack2(b_e[u], b_e[64 + u]);
    ull bgo = pack2(b_e[128 + u], b_e[192 + u]);
    float c_reg[7] = {0.f, 0.f, 0.f, 0.f, 0.f, 0.f, 0.f};

    // x prefetch slots (4 per thread covers 27*32=864 floats)
    const float* xp[4]; bool pval[4]; int pidx[4];
#pragma unroll
    for (int s = 0; s < 4; ++s) {
        int i = tid + s * NTHREADS;
        pidx[s] = i;
        int r = i >> 5, d = i & 31;
        int rc = (r < RMAX) ? r : 0;
        pval[s] = (i < RMAX * DD) && (r < cnt);
        xp[s] = x + (size_t)(rstart + rc) * (TT * DD) + DD + d;  // t = 1
    }
    __syncthreads();

    int cur = 0;
    // ===== encoder: 500 steps, 1 sync/step =====
    for (int t = 0; t < TT; ++t) {
        const int nxt = cur ^ 1;
        float xv[4] = {0.f, 0.f, 0.f, 0.f};
        const bool pre = (t + 1 < TT);
        if (pre) {
#pragma unroll
            for (int s = 0; s < 4; ++s) if (pval[s]) xv[s] = *xp[s];
        }
        if (seven)
            lstm_rows<7>(W4, xs4 + cur * (RMAX * 16), hs4 + cur * (RMAX * 32),
                         hs2 + nxt * (RMAX * HH), bif, bgo, c_reg, grp, u);
        else
            lstm_rows<6>(W4, xs4 + cur * (RMAX * 16), hs4 + cur * (RMAX * 32),
                         hs2 + nxt * (RMAX * HH), bif, bgo, c_reg, grp, u);
        if (pre) {
            float2* xsn = xs2 + nxt * (RMAX * DD);
#pragma unroll
            for (int s = 0; s < 4; ++s) {
                if (pidx[s] < RMAX * DD) xsn[pidx[s]] = make_float2(xv[s], xv[s]);
                xp[s] += DD;
            }
        }
        __syncthreads();
        cur = nxt;
    }

    // ===== swap to decoder weights =====
    load_gate_weights(W4, Wih_d, Whh_d, tid);
    for (int idx = tid; idx < (HH / 2) * DD; idx += NTHREADS) {
        int kp = idx >> 5, d = idx & 31;
        WoT2[idx] = make_float2(Wout[d * HH + 2 * kp], Wout[d * HH + 2 * kp + 1]);
    }
    for (int i = tid; i < RMAX * DD; i += NTHREADS)
        xs2[cur * (RMAX * DD) + i] = make_float2(0.f, 0.f);  // dec_in0 = 0
    bif = pack2(b_d[u], b_d[64 + u]);
    bgo = pack2(b_d[128 + u], b_d[192 + u]);
    const int dd   = u & 31;
    const int half = u >> 5;
    const float bo = bout[dd];
    // out-proj rows: r = grp + 4*(2j+half). half=0 -> grp,grp+8,grp+16,grp+24;
    // half=1 -> grp+4,grp+12,grp+20. nrj warp-uniform.
    const int nrj = (half == 0 && grp < 3) ? 4 : 3;
    int rj[4]; float* optr[4]; bool oval[4];
#pragma unroll
    for (int j = 0; j < 4; ++j) {
        int r = grp + 4 * (2 * j + half);
        rj[j] = (r < RMAX) ? r : 0;
        oval[j] = (j < nrj) && (r < cnt);
        optr[j] = outp + (size_t)(rstart + rj[j]) * (TT * DD) + dd;
    }
    __syncthreads();

    // ===== decoder: 500 autoregressive steps, 2 syncs/step =====
    for (int t = 0; t < TT; ++t) {
        const int nxt = cur ^ 1;
        if (seven)
            lstm_rows<7>(W4, xs4 + cur * (RMAX * 16), hs4 + cur * (RMAX * 32),
                         hs2 + nxt * (RMAX * HH), bif, bgo, c_reg, grp, u);
        else
            lstm_rows<6>(W4, xs4 + cur * (RMAX * 16), hs4 + cur * (RMAX * 32),
                         hs2 + nxt * (RMAX * HH), bif, bgo, c_reg, grp, u);
        __syncthreads();

        // out = h @ Wout^T + bout; feeds next step's input.
        {
            const float4* hs4n = hs4 + nxt * (RMAX * 32);
            ull acc2[4];
#pragma unroll
            for (int j = 0; j < 4; ++j) acc2[j] = pack2(bo, 0.f);
            if (nrj == 4) oproj_loop<4>(acc2, hs4n, WoT2u, rj, dd);
            else          oproj_loop<3>(acc2, hs4n, WoT2u, rj, dd);
            float2* xsn = xs2 + nxt * (RMAX * DD);
#pragma unroll
            for (int j = 0; j < 4; ++j) if (j < nrj) {
                float lo, hi; unpack2(lo, hi, acc2[j]);
                float val = lo + hi;
                if (oval[j]) *optr[j] = val;
                optr[j] += DD;
                xsn[rj[j] * DD + dd] = make_float2(val, val);
            }
        }
        __syncthreads();
        cur = nxt;
    }
}

extern "C" void kernel_launch(void* const* d_in, const int* in_sizes, int n_in,
                              void* d_out, int out_size)
{
    (void)in_sizes; (void)n_in; (void)out_size;
    cudaFuncSetAttribute(seq2seq_kernel,
                         cudaFuncAttributeMaxDynamicSharedMemorySize, SM_TOTAL);
    seq2seq_kernel<<<NGRID, NTHREADS, SM_TOTAL>>>(
        (const float*)d_in[0],
        (const float*)d_in[1], (const float*)d_in[2], (const float*)d_in[3],
        (const float*)d_in[4], (const float*)d_in[5], (const float*)d_in[6],
        (const float*)d_in[7], (const float*)d_in[8],
        (float*)d_out);
}

// round 10
// speedup vs baseline: 1.4245x; 1.0402x over previous
#include <cuda_runtime.h>

// Seq2Seq LSTM autoencoder, persistent-block design. GB300: 152 SMs.
// 256 threads = 4 row-groups x 64 units (thread = hidden unit, all 4 gates).
// Rows/thread: 7 (groups 0-2) or 6 (group 3), stride 4. c in registers,
// h/x in smem DUPLICATED float2 so one LDS.128 broadcast yields two packed
// f32x2 operands. Whh weights [k][u][i,f,g,o] float4 in smem; Wih weights
// REGISTER-CACHED per thread (time-invariant, 64 ull regs) to cut ~18% of
// L1 wavefronts. Phase-swapped encoder -> decoder.

#define NB 4096
#define TT 500
#define DD 32
#define HH 64
#define NGRID 152
#define NTHREADS 256
#define RMAX 27

#define SM_W4    0            // float4 [96*64]            = 98304 B
#define SM_WOUT  98304        // float2 [32*32] (k-pairs)  =  8192 B
#define SM_HS    106496       // float2 [2][27][64]        = 27648 B
#define SM_XS    134144       // float2 [2][27][32]        = 13824 B
#define SM_TOTAL 147968

typedef unsigned long long ull;

__device__ __forceinline__ ull pack2(float lo, float hi) {
    ull r; asm("mov.b64 %0, {%1, %2};" : "=l"(r) : "f"(lo), "f"(hi)); return r;
}
__device__ __forceinline__ void unpack2(float& lo, float& hi, ull v) {
    asm("mov.b64 {%0, %1}, %2;" : "=f"(lo), "=f"(hi) : "l"(v));
}
// Packed fp32x2 FMA (sm_100+; PTX-only, ptxas never auto-fuses)
#define FFMA2(acc, a, b) asm("fma.rn.f32x2 %0, %1, %2, %0;" : "+l"(acc) : "l"(a), "l"(b))

__device__ __forceinline__ float sigm(float v) {
    return __fdividef(1.f, 1.f + __expf(-v));
}
__device__ __forceinline__ float tanh_(float v) {
    return __fdividef(2.f, 1.f + __expf(-2.f * v)) - 1.f;
}

// One LSTM step for NR rows (rbase + i*4), unit u. x-part weights come from
// the register cache wih[64]; h-part weights from smem. Activations read as
// duplicated pairs, two-k-at-a-time via 16B broadcast loads.
template<int NR>
__device__ __forceinline__ void lstm_rows(
    const ull* __restrict__ wih, const float4* W4, const float4* xs4,
    const float4* hs4, float2* hsn,
    ull bif, ull bgo, float* c, int rbase, int u)
{
    ull aif[NR], ago[NR];
#pragma unroll
    for (int i = 0; i < NR; ++i) { aif[i] = bif; ago[i] = bgo; }
#pragma unroll
    for (int kp = 0; kp < DD / 2; ++kp) {     // FULL unroll: wih[] stays in regs
        ull w0x = wih[kp * 4 + 0], w0y = wih[kp * 4 + 1];
        ull w1x = wih[kp * 4 + 2], w1y = wih[kp * 4 + 3];
#pragma unroll
        for (int i = 0; i < NR; ++i) {
            ulonglong2 v = *reinterpret_cast<const ulonglong2*>(xs4 + (rbase + i * 4) * 16 + kp);
            FFMA2(aif[i], w0x, v.x);
            FFMA2(ago[i], w0y, v.x);
            FFMA2(aif[i], w1x, v.y);
            FFMA2(ago[i], w1y, v.y);
        }
    }
#pragma unroll 4
    for (int kp = 0; kp < HH / 2; ++kp) {
        ulonglong2 w0 = *reinterpret_cast<const ulonglong2*>(W4 + (DD + 2 * kp    ) * 64 + u);
        ulonglong2 w1 = *reinterpret_cast<const ulonglong2*>(W4 + (DD + 2 * kp + 1) * 64 + u);
#pragma unroll
        for (int i = 0; i < NR; ++i) {
            ulonglong2 v = *reinterpret_cast<const ulonglong2*>(hs4 + (rbase + i * 4) * 32 + kp);
            FFMA2(aif[i], w0.x, v.x);
            FFMA2(ago[i], w0.y, v.x);
            FFMA2(aif[i], w1.x, v.y);
            FFMA2(ago[i], w1.y, v.y);
        }
    }
#pragma unroll
    for (int i = 0; i < NR; ++i) {
        float ai, af, ag, ao;
        unpack2(ai, af, aif[i]);
        unpack2(ag, ao, ago[i]);
        float ig = sigm(ai), fg = sigm(af);
        float gg = tanh_(ag), og = sigm(ao);
        float cn = fg * c[i] + ig * gg;
        c[i] = cn;
        float h = og * tanh_(cn);
        hsn[(rbase + i * 4) * HH + u] = make_float2(h, h);
    }
}

// Decoder out-projection partial: k-pair outer, rows inner, f32x2 FMA.
template<int NRJ>
__device__ __forceinline__ void oproj_loop(
    ull* acc2, const float4* hs4n, const ull* WoT2u, const int* rj, int dd)
{
#pragma unroll 8
    for (int kp = 0; kp < HH / 2; ++kp) {
        ull wp = WoT2u[kp * DD + dd];
#pragma unroll
        for (int j = 0; j < NRJ; ++j) {
            float4 q = hs4n[rj[j] * 32 + kp];  // (hk,hk,hk1,hk1) broadcast
            ull hv = pack2(q.x, q.z);
            FFMA2(acc2[j], hv, wp);
        }
    }
}

__device__ __forceinline__ void load_gate_weights(
    float4* W4, const float* Wih, const float* Whh, int tid)
{
    for (int idx = tid; idx < 96 * 64; idx += NTHREADS) {
        int k = idx >> 6, uu = idx & 63;
        float4 w;
        if (k < DD) {
            w.x = Wih[(uu      ) * DD + k];
            w.y = Wih[(uu +  64) * DD + k];
            w.z = Wih[(uu + 128) * DD + k];
            w.w = Wih[(uu + 192) * DD + k];
        } else {
            int kk = k - DD;
            w.x = Whh[(uu      ) * HH + kk];
            w.y = Whh[(uu +  64) * HH + kk];
            w.z = Whh[(uu + 128) * HH + kk];
            w.w = Whh[(uu + 192) * HH + kk];
        }
        W4[idx] = w;
    }
}

// Refill the per-thread Wih register cache from smem (call after
// load_gate_weights + __syncthreads).
__device__ __forceinline__ void cache_wih(ull* wih, const float4* W4, int u)
{
#pragma unroll
    for (int kp = 0; kp < DD / 2; ++kp) {
        ulonglong2 w0 = *reinterpret_cast<const ulonglong2*>(W4 + (2 * kp    ) * 64 + u);
        ulonglong2 w1 = *reinterpret_cast<const ulonglong2*>(W4 + (2 * kp + 1) * 64 + u);
        wih[kp * 4 + 0] = w0.x;
        wih[kp * 4 + 1] = w0.y;
        wih[kp * 4 + 2] = w1.x;
        wih[kp * 4 + 3] = w1.y;
    }
}

__global__ void __launch_bounds__(NTHREADS, 1)
seq2seq_kernel(const float* __restrict__ x,
               const float* __restrict__ Wih_e, const float* __restrict__ Whh_e,
               const float* __restrict__ b_e,
               const float* __restrict__ Wih_d, const float* __restrict__ Whh_d,
               const float* __restrict__ b_d,
               const float* __restrict__ Wout, const float* __restrict__ bout,
               float* __restrict__ outp)
{
    extern __shared__ char sm[];
    float4*  W4    = reinterpret_cast<float4*>(sm + SM_W4);
    float2*  WoT2  = reinterpret_cast<float2*>(sm + SM_WOUT);
    const ull* WoT2u = reinterpret_cast<const ull*>(sm + SM_WOUT);
    float2*  hs2   = reinterpret_cast<float2*>(sm + SM_HS);
    float4*  hs4   = reinterpret_cast<float4*>(sm + SM_HS);
    float2*  xs2   = reinterpret_cast<float2*>(sm + SM_XS);
    float4*  xs4   = reinterpret_cast<float4*>(sm + SM_XS);

    const int tid = threadIdx.x;
    const int u   = tid & 63;   // hidden unit
    const int grp = tid >> 6;   // row group 0..3
    const int bid = blockIdx.x;
    const int rstart = (bid * NB) / NGRID;
    const int cnt = ((bid + 1) * NB) / NGRID - rstart;  // 26 or 27 real rows
    const bool seven = (grp < 3); // groups 0..2 own 7 rows (warp-uniform)

    // ---- encoder weights + init state ----
    load_gate_weights(W4, Wih_e, Whh_e, tid);
    for (int i = tid; i < 2 * RMAX * HH; i += NTHREADS) hs2[i] = make_float2(0.f, 0.f);
    for (int i = tid; i < RMAX * DD; i += NTHREADS) {
        int r = i >> 5, d = i & 31;
        float v = 0.f;
        if (r < cnt) v = x[(size_t)(rstart + r) * (TT * DD) + d];  // t = 0
        xs2[i] = make_float2(v, v);
    }
    ull bif = pack2(b_e[u], b_e[64 + u]);
    ull bgo = pack2(b_e[128 + u], b_e[192 + u]);
    float c_reg[7] = {0.f, 0.f, 0.f, 0.f, 0.f, 0.f, 0.f};

    // x prefetch slots (4 per thread covers 27*32=864 floats)
    const float* xp[4]; bool pval[4]; int pidx[4];
#pragma unroll
    for (int s = 0; s < 4; ++s) {
        int i = tid + s * NTHREADS;
        pidx[s] = i;
        int r = i >> 5, d = i & 31;
        int rc = (r < RMAX) ? r : 0;
        pval[s] = (i < RMAX * DD) && (r < cnt);
        xp[s] = x + (size_t)(rstart + rc) * (TT * DD) + DD + d;  // t = 1
    }
    __syncthreads();

    ull wih[64];
    cache_wih(wih, W4, u);      // encoder Wih -> registers

    int cur = 0;
    // ===== encoder: 500 steps, 1 sync/step =====
    for (int t = 0; t < TT; ++t) {
        const int nxt = cur ^ 1;
        float xv[4] = {0.f, 0.f, 0.f, 0.f};
        const bool pre = (t + 1 < TT);
        if (pre) {
#pragma unroll
            for (int s = 0; s < 4; ++s) if (pval[s]) xv[s] = *xp[s];
        }
        if (seven)
            lstm_rows<7>(wih, W4, xs4 + cur * (RMAX * 16), hs4 + cur * (RMAX * 32),
                         hs2 + nxt * (RMAX * HH), bif, bgo, c_reg, grp, u);
        else
            lstm_rows<6>(wih, W4, xs4 + cur * (RMAX * 16), hs4 + cur * (RMAX * 32),
                         hs2 + nxt * (RMAX * HH), bif, bgo, c_reg, grp, u);
        if (pre) {
            float2* xsn = xs2 + nxt * (RMAX * DD);
#pragma unroll
            for (int s = 0; s < 4; ++s) {
                if (pidx[s] < RMAX * DD) xsn[pidx[s]] = make_float2(xv[s], xv[s]);
                xp[s] += DD;
            }
        }
        __syncthreads();
        cur = nxt;
    }

    // ===== swap to decoder weights =====
    load_gate_weights(W4, Wih_d, Whh_d, tid);
    for (int idx = tid; idx < (HH / 2) * DD; idx += NTHREADS) {
        int kp = idx >> 5, d = idx & 31;
        WoT2[idx] = make_float2(Wout[d * HH + 2 * kp], Wout[d * HH + 2 * kp + 1]);
    }
    for (int i = tid; i < RMAX * DD; i += NTHREADS)
        xs2[cur * (RMAX * DD) + i] = make_float2(0.f, 0.f);  // dec_in0 = 0
    bif = pack2(b_d[u], b_d[64 + u]);
    bgo = pack2(b_d[128 + u], b_d[192 + u]);
    const int dd   = u & 31;
    const int half = u >> 5;
    const float bo = bout[dd];
    // out-proj rows: r = grp + 4*(2j+half). half=0 -> grp,grp+8,grp+16,grp+24;
    // half=1 -> grp+4,grp+12,grp+20. nrj warp-uniform.
    const int nrj = (half == 0 && grp < 3) ? 4 : 3;
    int rj[4]; float* optr[4]; bool oval[4];
#pragma unroll
    for (int j = 0; j < 4; ++j) {
        int r = grp + 4 * (2 * j + half);
        rj[j] = (r < RMAX) ? r : 0;
        oval[j] = (j < nrj) && (r < cnt);
        optr[j] = outp + (size_t)(rstart + rj[j]) * (TT * DD) + dd;
    }
    __syncthreads();

    cache_wih(wih, W4, u);      // decoder Wih -> registers

    // ===== decoder: 500 autoregressive steps, 2 syncs/step =====
    for (int t = 0; t < TT; ++t) {
        const int nxt = cur ^ 1;
        if (seven)
            lstm_rows<7>(wih, W4, xs4 + cur * (RMAX * 16), hs4 + cur * (RMAX * 32),
                         hs2 + nxt * (RMAX * HH), bif, bgo, c_reg, grp, u);
        else
            lstm_rows<6>(wih, W4, xs4 + cur * (RMAX * 16), hs4 + cur * (RMAX * 32),
                         hs2 + nxt * (RMAX * HH), bif, bgo, c_reg, grp, u);
        __syncthreads();

        // out = h @ Wout^T + bout; feeds next step's input.
        {
            const float4* hs4n = hs4 + nxt * (RMAX * 32);
            ull acc2[4];
#pragma unroll
            for (int j = 0; j < 4; ++j) acc2[j] = pack2(bo, 0.f);
            if (nrj == 4) oproj_loop<4>(acc2, hs4n, WoT2u, rj, dd);
            else          oproj_loop<3>(acc2, hs4n, WoT2u, rj, dd);
            float2* xsn = xs2 + nxt * (RMAX * DD);
#pragma unroll
            for (int j = 0; j < 4; ++j) if (j < nrj) {
                float lo, hi; unpack2(lo, hi, acc2[j]);
                float val = lo + hi;
                if (oval[j]) *optr[j] = val;
                optr[j] += DD;
                xsn[rj[j] * DD + dd] = make_float2(val, val);
            }
        }
        __syncthreads();
        cur = nxt;
    }
}

extern "C" void kernel_launch(void* const* d_in, const int* in_sizes, int n_in,
                              void* d_out, int out_size)
{
    (void)in_sizes; (void)n_in; (void)out_size;
    cudaFuncSetAttribute(seq2seq_kernel,
                         cudaFuncAttributeMaxDynamicSharedMemorySize, SM_TOTAL);
    seq2seq_kernel<<<NGRID, NTHREADS, SM_TOTAL>>>(
        (const float*)d_in[0],
        (const float*)d_in[1], (const float*)d_in[2], (const float*)d_in[3],
        (const float*)d_in[4], (const float*)d_in[5], (const float*)d_in[6],
        (const float*)d_in[7], (const float*)d_in[8],
        (float*)d_out);
}

// round 14
// speedup vs baseline: 1.6989x; 1.1926x over previous
#include <cuda_runtime.h>

// Seq2Seq LSTM autoencoder, persistent-block, row-pair-packed f32x2.
// GB300: 152 SMs, 1 block/SM, 256 threads = 4 grps x 64 units.
// State TRANSPOSED + non-duplicated: hs[k][28], xs[k][28] floats. One 16B
// broadcast LDS per (k, row-quad) gives 4 rows; (h_r0,h_r1) is directly an
// f32x2 operand. Weights [k][u][i,f,g,o] float4 (1 LDS.128/k) + dup MOVs
// on the ALU pipe. Row ownership: grp0 rows 0-7, grp1 8-15, grp2 16-21,
// grp3 22-27 (pair counts 4,4,3,3 -> each SMSP sums 7 pairs, fma-balanced).

#define NB 4096
#define TT 500
#define DD 32
#define HH 64
#define NGRID 152
#define NTHREADS 256
#define RMAX 28            // 27 real rows max + 1 pad

#define HS_F (HH * RMAX)   // 1792 floats per buffer
#define XS_F (DD * RMAX)   // 896 floats per buffer

#define SM_W4    0                      // float4 [96*64]  = 98304 B
#define SM_WOUT  98304                  // ull   [64*32]   = 16384 B (dup Wout)
#define SM_HS    114688                 // float [2][64][28] = 14336 B
#define SM_XS    129024                 // float [2][32][28] =  7168 B
#define SM_TOTAL 136192

typedef unsigned long long ull;

__device__ __forceinline__ ull pack2(float lo, float hi) {
    ull r; asm("mov.b64 %0, {%1, %2};" : "=l"(r) : "f"(lo), "f"(hi)); return r;
}
__device__ __forceinline__ void unpack2(float& lo, float& hi, ull v) {
    asm("mov.b64 {%0, %1}, %2;" : "=f"(lo), "=f"(hi) : "l"(v));
}
// Packed fp32x2 FMA (sm_100+; PTX-only)
#define FFMA2(acc, a, b) asm("fma.rn.f32x2 %0, %1, %2, %0;" : "+l"(acc) : "l"(a), "l"(b))

__device__ __forceinline__ float sigm(float v) {
    return __fdividef(1.f, 1.f + __expf(-v));
}
__device__ __forceinline__ float tanh_(float v) {
    return __fdividef(2.f, 1.f + __expf(-2.f * v)) - 1.f;
}

// One LSTM step for this thread's rows. NP = row-pairs (4 or 3).
// QF: true = quad(s) first (grp0/1/2); false = pair then quad (grp3).
template<int NP, bool QF>
__device__ __forceinline__ void gate_step(
    const float4* __restrict__ W4, const float* __restrict__ xsb,
    const float* __restrict__ hsb, float* __restrict__ hsn,
    const ull* bd, float* c, int rowbase, int u)
{
    ull ai[NP], af[NP], ag[NP], ao[NP];
#pragma unroll
    for (int p = 0; p < NP; ++p) { ai[p] = bd[0]; af[p] = bd[1]; ag[p] = bd[2]; ao[p] = bd[3]; }

#define GATE_K(KIDX, COL) {                                                   \
        float4 wq = W4[(KIDX) * 64 + u];                                      \
        ull wi2 = pack2(wq.x, wq.x), wf2 = pack2(wq.y, wq.y);                 \
        ull wg2 = pack2(wq.z, wq.z), wo2 = pack2(wq.w, wq.w);                 \
        ull hv[NP];                                                           \
        if constexpr (NP == 4) {                                              \
            ulonglong2 a = *reinterpret_cast<const ulonglong2*>((COL) + rowbase);     \
            ulonglong2 b = *reinterpret_cast<const ulonglong2*>((COL) + rowbase + 4); \
            hv[0] = a.x; hv[1] = a.y; hv[2] = b.x; hv[3] = b.y;               \
        } else if constexpr (QF) {                                            \
            ulonglong2 a = *reinterpret_cast<const ulonglong2*>((COL) + rowbase);     \
            hv[0] = a.x; hv[1] = a.y;                                         \
            hv[2] = *reinterpret_cast<const ull*>((COL) + rowbase + 4);       \
        } else {                                                              \
            hv[0] = *reinterpret_cast<const ull*>((COL) + rowbase);           \
            ulonglong2 a = *reinterpret_cast<const ulonglong2*>((COL) + rowbase + 2); \
            hv[1] = a.x; hv[2] = a.y;                                         \
        }                                                                     \
        _Pragma("unroll")                                                     \
        for (int p = 0; p < NP; ++p) {                                        \
            FFMA2(ai[p], wi2, hv[p]);                                         \
            FFMA2(af[p], wf2, hv[p]);                                         \
            FFMA2(ag[p], wg2, hv[p]);                                         \
            FFMA2(ao[p], wo2, hv[p]);                                         \
        }                                                                     \
    }

#pragma unroll 8
    for (int k = 0; k < DD; ++k) GATE_K(k, xsb + k * RMAX)
#pragma unroll 8
    for (int k = 0; k < HH; ++k) GATE_K(DD + k, hsb + k * RMAX)
#undef GATE_K

#pragma unroll
    for (int p = 0; p < NP; ++p) {
        float i0, i1, f0, f1, g0, g1, o0, o1;
        unpack2(i0, i1, ai[p]);
        unpack2(f0, f1, af[p]);
        unpack2(g0, g1, ag[p]);
        unpack2(o0, o1, ao[p]);
        float cn0 = sigm(f0) * c[2 * p]     + sigm(i0) * tanh_(g0);
        float cn1 = sigm(f1) * c[2 * p + 1] + sigm(i1) * tanh_(g1);
        c[2 * p]     = cn0;
        c[2 * p + 1] = cn1;
        float h0 = sigm(o0) * tanh_(cn0);
        float h1 = sigm(o1) * tanh_(cn1);
        *reinterpret_cast<ull*>(hsn + u * RMAX + rowbase + 2 * p) = pack2(h0, h1);
    }
}

__device__ __forceinline__ void load_gate_weights(
    float4* W4, const float* Wih, const float* Whh, int tid)
{
    for (int idx = tid; idx < 96 * 64; idx += NTHREADS) {
        int k = idx >> 6, uu = idx & 63;
        float4 w;
        if (k < DD) {
            w.x = Wih[(uu      ) * DD + k];
            w.y = Wih[(uu +  64) * DD + k];
            w.z = Wih[(uu + 128) * DD + k];
            w.w = Wih[(uu + 192) * DD + k];
        } else {
            int kk = k - DD;
            w.x = Whh[(uu      ) * HH + kk];
            w.y = Whh[(uu +  64) * HH + kk];
            w.z = Whh[(uu + 128) * HH + kk];
            w.w = Whh[(uu + 192) * HH + kk];
        }
        W4[idx] = w;
    }
}

__global__ void __launch_bounds__(NTHREADS, 1)
seq2seq_kernel(const float* __restrict__ x,
               const float* __restrict__ Wih_e, const float* __restrict__ Whh_e,
               const float* __restrict__ b_e,
               const float* __restrict__ Wih_d, const float* __restrict__ Whh_d,
               const float* __restrict__ b_d,
               const float* __restrict__ Wout, const float* __restrict__ bout,
               float* __restrict__ outp)
{
    extern __shared__ char sm[];
    float4* W4   = reinterpret_cast<float4*>(sm + SM_W4);
    ull*    WoTd = reinterpret_cast<ull*>(sm + SM_WOUT);
    float*  hsA  = reinterpret_cast<float*>(sm + SM_HS);   // [2][HS_F]
    float*  xsA  = reinterpret_cast<float*>(sm + SM_XS);   // [2][XS_F]

    const int tid = threadIdx.x;
    const int u   = tid & 63;
    const int grp = tid >> 6;
    const int bid = blockIdx.x;
    const int rstart = (bid * NB) / NGRID;
    const int cnt = ((bid + 1) * NB) / NGRID - rstart;     // 26 or 27

    // ---- encoder weights + state init ----
    load_gate_weights(W4, Wih_e, Whh_e, tid);
    for (int i = tid; i < 2 * HS_F; i += NTHREADS) hsA[i] = 0.f;
    for (int i = tid; i < XS_F; i += NTHREADS) {
        int r = i >> 5, d = i & 31;
        float v = 0.f;
        if (r < cnt) v = x[(size_t)(rstart + r) * (TT * DD) + d];   // t = 0
        xsA[d * RMAX + r] = v;                                      // buf 0, transposed
    }
    ull bd[4];
    bd[0] = pack2(b_e[u], b_e[u]);
    bd[1] = pack2(b_e[64 + u], b_e[64 + u]);
    bd[2] = pack2(b_e[128 + u], b_e[128 + u]);
    bd[3] = pack2(b_e[192 + u], b_e[192 + u]);
    float c_reg[8] = {0.f, 0.f, 0.f, 0.f, 0.f, 0.f, 0.f, 0.f};

    // x prefetch slots (4 x 256 covers 28*32 = 896 slots)
    const float* xp[4]; bool pval[4]; int poff[4]; bool pin[4];
#pragma unroll
    for (int s = 0; s < 4; ++s) {
        int i = tid + s * NTHREADS;
        int r = i >> 5, d = i & 31;
        int rc = (r < RMAX && r < cnt) ? r : 0;
        pin[s]  = (i < XS_F);
        pval[s] = pin[s] && (r < cnt);
        poff[s] = d * RMAX + ((r < RMAX) ? r : 0);
        xp[s] = x + (size_t)(rstart + rc) * (TT * DD) + DD + d;     // t = 1
    }
    __syncthreads();

    int cur = 0;
    // ===== encoder: 500 steps, 1 sync/step =====
    for (int t = 0; t < TT; ++t) {
        const int nxt = cur ^ 1;
        float xv[4] = {0.f, 0.f, 0.f, 0.f};
        const bool pre = (t + 1 < TT);
        if (pre) {
#pragma unroll
            for (int s = 0; s < 4; ++s) if (pval[s]) xv[s] = *xp[s];
        }
        const float* xsb = xsA + cur * XS_F;
        const float* hsb = hsA + cur * HS_F;
        float*       hsn = hsA + nxt * HS_F;
        if      (grp == 0) gate_step<4, true >(W4, xsb, hsb, hsn, bd, c_reg, 0,  u);
        else if (grp == 1) gate_step<4, true >(W4, xsb, hsb, hsn, bd, c_reg, 8,  u);
        else if (grp == 2) gate_step<3, true >(W4, xsb, hsb, hsn, bd, c_reg, 16, u);
        else               gate_step<3, false>(W4, xsb, hsb, hsn, bd, c_reg, 22, u);
        if (pre) {
            float* xsn = xsA + nxt * XS_F;
#pragma unroll
            for (int s = 0; s < 4; ++s) {
                if (pin[s]) xsn[poff[s]] = xv[s];
                xp[s] += DD;
            }
        }
        __syncthreads();
        cur = nxt;
    }

    // ===== swap to decoder weights =====
    load_gate_weights(W4, Wih_d, Whh_d, tid);
    for (int idx = tid; idx < HH * DD; idx += NTHREADS) {
        int k = idx >> 5, d = idx & 31;
        float w = Wout[d * HH + k];
        WoTd[idx] = pack2(w, w);           // WoTd[k*32+d] = (w, w)
    }
    for (int i = tid; i < XS_F; i += NTHREADS)
        xsA[cur * XS_F + i] = 0.f;          // dec_in0 = 0
    bd[0] = pack2(b_d[u], b_d[u]);
    bd[1] = pack2(b_d[64 + u], b_d[64 + u]);
    bd[2] = pack2(b_d[128 + u], b_d[128 + u]);
    bd[3] = pack2(b_d[192 + u], b_d[192 + u]);

    // out-projection: slot = grp*2 + half owns pairs {2*slot, 2*slot+1}
    const int dd   = u & 31;
    const int half = u >> 5;
    const int slot = grp * 2 + half;
    const float bo = bout[dd];
    bool pv[2]; bool ov0[2], ov1[2]; float* o0p[2]; float* o1p[2];
    int r2p[2]; int xoff[2];
#pragma unroll
    for (int j = 0; j < 2; ++j) {
        int p = slot * 2 + j;
        pv[j] = (p < 14);
        int r0 = (p < 14) ? 2 * p : 0;
        r2p[j]  = r0;
        ov0[j] = pv[j] && (r0 < cnt);
        ov1[j] = pv[j] && (r0 + 1 < cnt);
        o0p[j] = outp + (size_t)(rstart + r0) * (TT * DD) + dd;
        o1p[j] = outp + (size_t)(rstart + r0 + 1) * (TT * DD) + dd;
        xoff[j] = dd * RMAX + r0;
    }
    __syncthreads();

    // ===== decoder: 500 autoregressive steps, 2 syncs/step =====
    for (int t = 0; t < TT; ++t) {
        const int nxt = cur ^ 1;
        const float* xsb = xsA + cur * XS_F;
        const float* hsb = hsA + cur * HS_F;
        float*       hsn = hsA + nxt * HS_F;
        if      (grp == 0) gate_step<4, true >(W4, xsb, hsb, hsn, bd, c_reg, 0,  u);
        else if (grp == 1) gate_step<4, true >(W4, xsb, hsb, hsn, bd, c_reg, 8,  u);
        else if (grp == 2) gate_step<3, true >(W4, xsb, hsb, hsn, bd, c_reg, 16, u);
        else               gate_step<3, false>(W4, xsb, hsb, hsn, bd, c_reg, 22, u);
        __syncthreads();

        // out = h @ Wout^T + bout (row-pair packed), feeds next x
        {
            float* xsn = xsA + nxt * XS_F;
#pragma unroll
            for (int j = 0; j < 2; ++j) {
                if (!pv[j]) continue;      // warp-uniform (slot==7 only)
                ull acc = pack2(bo, bo);
#pragma unroll 8
                for (int k = 0; k < HH; ++k) {
                    ull wv = WoTd[k * DD + dd];
                    ull hv = *reinterpret_cast<const ull*>(hsn + k * RMAX + r2p[j]);
                    FFMA2(acc, hv, wv);
                }
                float o0, o1; unpack2(o0, o1, acc);
                if (ov0[j]) *o0p[j] = o0;
                if (ov1[j]) *o1p[j] = o1;
                o0p[j] += DD; o1p[j] += DD;
                *reinterpret_cast<ull*>(xsn + xoff[j]) = pack2(o0, o1);
            }
        }
        __syncthreads();
        cur = nxt;
    }
}

extern "C" void kernel_launch(void* const* d_in, const int* in_sizes, int n_in,
                              void* d_out, int out_size)
{
    (void)in_sizes; (void)n_in; (void)out_size;
    cudaFuncSetAttribute(seq2seq_kernel,
                         cudaFuncAttributeMaxDynamicSharedMemorySize, SM_TOTAL);
    seq2seq_kernel<<<NGRID, NTHREADS, SM_TOTAL>>>(
        (const float*)d_in[0],
        (const float*)d_in[1], (const float*)d_in[2], (const float*)d_in[3],
        (const float*)d_in[4], (const float*)d_in[5], (const float*)d_in[6],
        (const float*)d_in[7], (const float*)d_in[8],
        (float*)d_out);
}